// round 1
// baseline (speedup 1.0000x reference)
#include <cuda_runtime.h>

// Problem constants
//  x : [4, 128, 384, 384] f32
//  w1: [128, 128, 3, 3]   f32
//  w2: [256, 128, 3, 3]   f32
//  out: [4, 256, 128, 9]  f32  (softmax over last 1152 per (b, o))
//
// Pipeline:
//  1) conv_gemm_kernel: implicit GEMM, M=384 (co: 128 of w1 + 256 of w2),
//     N=589824 (b,h,w), K=1152 (ci,p,q). Writes Y in phase-major
//     ("pre-unfolded") layout g_Y[b][co][k9][hp*128+wp].
//  2) gram_kernel: per (b, k): C[o,i] = sum_l y2[o,l]*y1[i,l], tiled GEMM,
//     split-K over l with atomicAdd into g_logits[b][o][i][k].
//  3) softmax_kernel: scale by 1/sqrt(1152), softmax over (i,k)=1152, -> d_out.

#define KDIM 1152

// Scratch (device globals; no allocation inside kernel_launch)
__device__ float g_Y[(size_t)4 * 384 * 9 * 16384];   // ~906 MB
__device__ float g_logits[4 * 256 * 128 * 9];        // 4.7 MB

// ---------------------------------------------------------------------------
// Kernel 1: implicit-GEMM conv (both weight sets fused along M)
// Grid: (4608, 3), Block: 256. Tile 128(M) x 128(N) x 8(K), 8x8 microtile.
// ---------------------------------------------------------------------------
__global__ __launch_bounds__(256, 2)
void conv_gemm_kernel(const float* __restrict__ x,
                      const float* __restrict__ w1,
                      const float* __restrict__ w2)
{
    __shared__ float As[2][8][128];   // [buf][kk][co]
    __shared__ float Bs[2][8][128];   // [buf][kk][n_local]

    const int tid = threadIdx.x;
    const int tx = tid & 15;          // N direction (8 cols each)
    const int ty = tid >> 4;          // M direction (8 rows each)

    const int n0 = blockIdx.x * 128;          // flat (b,h,w) tile start
    const int b  = n0 / 147456;               // 147456 = 384*384
    const int rm = n0 - b * 147456;
    const int h  = rm / 384;                  // 128 | 384 => no h crossing
    const int w0 = rm - h * 384;
    const int co0 = blockIdx.y * 128;

    // A (weights) loader: 2 threads per row, one float4 each
    const int a_row = tid >> 1;               // 0..127
    const int a_col = (tid & 1) * 4;          // 0 or 4
    const float* Aptr;
    {
        const int co = co0 + a_row;
        Aptr = (co < 128) ? (w1 + (size_t)co * KDIM)
                          : (w2 + (size_t)(co - 128) * KDIM);
        Aptr += a_col;
    }

    // B (im2col of x) loader: one kk row of 128 per warp-slice
    const int b_kk   = tid >> 5;              // 0..7
    const int b_lane = tid & 31;

    float acc[8][8];
    #pragma unroll
    for (int i = 0; i < 8; i++)
        #pragma unroll
        for (int j = 0; j < 8; j++) acc[i][j] = 0.f;

    float4 a_reg;
    float  b_reg[4];

    // ---- prologue: chunk 0 ----
    {
        a_reg = *(const float4*)(Aptr);
        const int k  = b_kk;
        const int ci = k / 9;
        const int r  = k - ci * 9;
        const int p  = r / 3;
        const int q  = r - p * 3;
        const int row = h + p - 1;
        const bool rowok = (unsigned)row < 384u;
        const float* xrow = x + ((size_t)(b * 128 + ci) * 384 + row) * 384;
        #pragma unroll
        for (int j = 0; j < 4; j++) {
            const int col = w0 + b_lane + 32 * j + q - 1;
            b_reg[j] = (rowok && (unsigned)col < 384u) ? xrow[col] : 0.f;
        }
        As[0][a_col + 0][a_row] = a_reg.x;
        As[0][a_col + 1][a_row] = a_reg.y;
        As[0][a_col + 2][a_row] = a_reg.z;
        As[0][a_col + 3][a_row] = a_reg.w;
        #pragma unroll
        for (int j = 0; j < 4; j++) Bs[0][b_kk][b_lane + 32 * j] = b_reg[j];
        __syncthreads();
    }

    // ---- main loop: 144 K-chunks of 8 ----
    for (int kt = 0; kt < 144; kt++) {
        const int cur = kt & 1;

        if (kt < 143) {  // prefetch next chunk into registers
            const int k0 = (kt + 1) * 8;
            a_reg = *(const float4*)(Aptr + k0);
            const int k  = k0 + b_kk;
            const int ci = k / 9;
            const int r  = k - ci * 9;
            const int p  = r / 3;
            const int q  = r - p * 3;
            const int row = h + p - 1;
            const bool rowok = (unsigned)row < 384u;
            const float* xrow = x + ((size_t)(b * 128 + ci) * 384 + row) * 384;
            #pragma unroll
            for (int j = 0; j < 4; j++) {
                const int col = w0 + b_lane + 32 * j + q - 1;
                b_reg[j] = (rowok && (unsigned)col < 384u) ? xrow[col] : 0.f;
            }
        }

        #pragma unroll
        for (int kk = 0; kk < 8; kk++) {
            const float4 a0 = *(const float4*)&As[cur][kk][ty * 8];
            const float4 a1 = *(const float4*)&As[cur][kk][ty * 8 + 4];
            const float4 b0 = *(const float4*)&Bs[cur][kk][tx * 8];
            const float4 b1 = *(const float4*)&Bs[cur][kk][tx * 8 + 4];
            const float av[8] = {a0.x, a0.y, a0.z, a0.w, a1.x, a1.y, a1.z, a1.w};
            const float bv[8] = {b0.x, b0.y, b0.z, b0.w, b1.x, b1.y, b1.z, b1.w};
            #pragma unroll
            for (int i = 0; i < 8; i++)
                #pragma unroll
                for (int j = 0; j < 8; j++)
                    acc[i][j] = fmaf(av[i], bv[j], acc[i][j]);
        }

        if (kt < 143) {
            const int nxt = cur ^ 1;
            As[nxt][a_col + 0][a_row] = a_reg.x;
            As[nxt][a_col + 1][a_row] = a_reg.y;
            As[nxt][a_col + 2][a_row] = a_reg.z;
            As[nxt][a_col + 3][a_row] = a_reg.w;
            #pragma unroll
            for (int j = 0; j < 4; j++) Bs[nxt][b_kk][b_lane + 32 * j] = b_reg[j];
            __syncthreads();
        }
    }

    // ---- epilogue: write phase-major ("unfolded") layout ----
    const int hm = h % 3, hd = h / 3;
    int kp[8], wp[8];
    #pragma unroll
    for (int jj = 0; jj < 8; jj++) {
        const int w = w0 + tx * 8 + jj;
        kp[jj] = hm * 3 + (w % 3);
        wp[jj] = w / 3;
    }
    #pragma unroll
    for (int ii = 0; ii < 8; ii++) {
        const int co = co0 + ty * 8 + ii;
        const size_t base = (size_t)(b * 384 + co) * 9;
        #pragma unroll
        for (int jj = 0; jj < 8; jj++) {
            g_Y[(base + kp[jj]) * 16384 + (size_t)hd * 128 + wp[jj]] = acc[ii][jj];
        }
    }
}

// ---------------------------------------------------------------------------
// Kernel 2: per-(b, k) gram GEMM with split-K over l and atomic accumulation.
// Grid: (8 l-splits, 2 o-tiles, 36 (b,k)), Block: 256.
// Tile 128(o) x 128(i) x 8(l-chunk), 2048 l per block.
// ---------------------------------------------------------------------------
__global__ __launch_bounds__(256, 2)
void gram_kernel()
{
    __shared__ float As[2][8][128];   // [buf][kk][o]
    __shared__ float Bs[2][8][128];   // [buf][kk][i]

    const int tid = threadIdx.x;
    const int tx = tid & 15;
    const int ty = tid >> 4;

    const int bk = blockIdx.z;
    const int b  = bk / 9;
    const int k  = bk - b * 9;
    const int o0 = blockIdx.y * 128;
    const int l0 = blockIdx.x * 2048;

    const int ld_row = tid >> 1;              // 0..127
    const int ld_col = (tid & 1) * 4;         // 0 or 4

    const float* Aptr = g_Y + ((size_t)(b * 384 + 128 + o0 + ld_row) * 9 + k) * 16384
                        + l0 + ld_col;        // y2 rows (co = 128 + o)
    const float* Bptr = g_Y + ((size_t)(b * 384 + ld_row) * 9 + k) * 16384
                        + l0 + ld_col;        // y1 rows (co = i)

    float acc[8][8];
    #pragma unroll
    for (int i = 0; i < 8; i++)
        #pragma unroll
        for (int j = 0; j < 8; j++) acc[i][j] = 0.f;

    float4 a_reg = *(const float4*)(Aptr);
    float4 b_reg = *(const float4*)(Bptr);
    As[0][ld_col + 0][ld_row] = a_reg.x;
    As[0][ld_col + 1][ld_row] = a_reg.y;
    As[0][ld_col + 2][ld_row] = a_reg.z;
    As[0][ld_col + 3][ld_row] = a_reg.w;
    Bs[0][ld_col + 0][ld_row] = b_reg.x;
    Bs[0][ld_col + 1][ld_row] = b_reg.y;
    Bs[0][ld_col + 2][ld_row] = b_reg.z;
    Bs[0][ld_col + 3][ld_row] = b_reg.w;
    __syncthreads();

    for (int kt = 0; kt < 256; kt++) {
        const int cur = kt & 1;
        if (kt < 255) {
            a_reg = *(const float4*)(Aptr + (kt + 1) * 8);
            b_reg = *(const float4*)(Bptr + (kt + 1) * 8);
        }
        #pragma unroll
        for (int kk = 0; kk < 8; kk++) {
            const float4 a0 = *(const float4*)&As[cur][kk][ty * 8];
            const float4 a1 = *(const float4*)&As[cur][kk][ty * 8 + 4];
            const float4 b0 = *(const float4*)&Bs[cur][kk][tx * 8];
            const float4 b1 = *(const float4*)&Bs[cur][kk][tx * 8 + 4];
            const float av[8] = {a0.x, a0.y, a0.z, a0.w, a1.x, a1.y, a1.z, a1.w};
            const float bv[8] = {b0.x, b0.y, b0.z, b0.w, b1.x, b1.y, b1.z, b1.w};
            #pragma unroll
            for (int i = 0; i < 8; i++)
                #pragma unroll
                for (int j = 0; j < 8; j++)
                    acc[i][j] = fmaf(av[i], bv[j], acc[i][j]);
        }
        if (kt < 255) {
            const int nxt = cur ^ 1;
            As[nxt][ld_col + 0][ld_row] = a_reg.x;
            As[nxt][ld_col + 1][ld_row] = a_reg.y;
            As[nxt][ld_col + 2][ld_row] = a_reg.z;
            As[nxt][ld_col + 3][ld_row] = a_reg.w;
            Bs[nxt][ld_col + 0][ld_row] = b_reg.x;
            Bs[nxt][ld_col + 1][ld_row] = b_reg.y;
            Bs[nxt][ld_col + 2][ld_row] = b_reg.z;
            Bs[nxt][ld_col + 3][ld_row] = b_reg.w;
            __syncthreads();
        }
    }

    // logits layout: [b][o][i][k]  (k innermost, 9)
    #pragma unroll
    for (int ii = 0; ii < 8; ii++) {
        const int o = o0 + ty * 8 + ii;
        float* dst = g_logits + ((size_t)(b * 256 + o) * 128) * 9 + k;
        #pragma unroll
        for (int jj = 0; jj < 8; jj++) {
            const int i = tx * 8 + jj;
            atomicAdd(dst + (size_t)i * 9, acc[ii][jj]);
        }
    }
}

// ---------------------------------------------------------------------------
// Kernel 0: zero the logits accumulator (must run each launch; atomics append)
// ---------------------------------------------------------------------------
__global__ void zero_logits_kernel()
{
    const int i = blockIdx.x * 256 + threadIdx.x;
    if (i < 4 * 256 * 128 * 9) g_logits[i] = 0.f;
}

// ---------------------------------------------------------------------------
// Kernel 3: scale + row softmax over 1152, rows = (b, o) = 1024
// ---------------------------------------------------------------------------
__global__ void softmax_kernel(float* __restrict__ out)
{
    const int row = blockIdx.x;                 // 0..1023
    const float* in = g_logits + (size_t)row * 1152;
    float* op = out + (size_t)row * 1152;
    const float sc = 0.029462782549439484f;     // 1/sqrt(1152)

    __shared__ float red[256];
    const int tid = threadIdx.x;

    float m = -1e30f;
    for (int j = tid; j < 1152; j += 256) m = fmaxf(m, in[j] * sc);
    red[tid] = m;
    __syncthreads();
    for (int s = 128; s > 0; s >>= 1) {
        if (tid < s) red[tid] = fmaxf(red[tid], red[tid + s]);
        __syncthreads();
    }
    m = red[0];
    __syncthreads();

    float sum = 0.f;
    for (int j = tid; j < 1152; j += 256) {
        const float e = expf(in[j] * sc - m);
        op[j] = e;
        sum += e;
    }
    red[tid] = sum;
    __syncthreads();
    for (int s = 128; s > 0; s >>= 1) {
        if (tid < s) red[tid] += red[tid + s];
        __syncthreads();
    }
    const float inv = 1.0f / red[0];
    for (int j = tid; j < 1152; j += 256) op[j] *= inv;
}

// ---------------------------------------------------------------------------
extern "C" void kernel_launch(void* const* d_in, const int* in_sizes, int n_in,
                              void* d_out, int out_size)
{
    const float* x  = (const float*)d_in[0];   // [4,128,384,384]
    const float* w1 = (const float*)d_in[1];   // [128,128,3,3]
    const float* w2 = (const float*)d_in[2];   // [256,128,3,3]
    float* out = (float*)d_out;                // [4,256,128,9]

    conv_gemm_kernel<<<dim3(4608, 3), 256>>>(x, w1, w2);
    zero_logits_kernel<<<4608, 256>>>();
    gram_kernel<<<dim3(8, 2, 36), 256>>>();
    softmax_kernel<<<1024, 256>>>(out);
}

// round 15
// speedup vs baseline: 1.5272x; 1.5272x over previous
#include <cuda_runtime.h>
#include <cuda_bf16.h>
#include <cstdint>

// x : [4, 128, 384, 384] f32 | w1: [128,128,3,3] | w2: [256,128,3,3]
// out: [4, 256, 128, 9] f32 softmax over last 1152 per (b, o)
//
// conv_mma: mma.sync.m16n8k16 bf16 warp-tiled GEMM (sm_80 PTX; compiles at
// compute_103 — tcgen05 is NOT available under this harness's PTX target).
// 3-term split-bf16 product (hh + hl + lh), fp32 accumulators in registers.
// cp.async double-buffered tiles, SW128 XOR swizzle, zero-fill for halo.

#define KDIM 1152

// ---------------- scratch (device globals; no runtime allocation) ----------
__device__ float g_Y[(size_t)4 * 384 * 9 * 16384];          // ~906 MB
__device__ float g_logits[4 * 256 * 128 * 9];
__device__ __nv_bfloat16 g_xh[(size_t)4 * 384 * 384 * 128]; // NHWC hi
__device__ __nv_bfloat16 g_xl[(size_t)4 * 384 * 384 * 128]; // NHWC lo
__device__ __nv_bfloat16 g_wh[384 * KDIM];                  // [co][pq*128+ci]
__device__ __nv_bfloat16 g_wl[384 * KDIM];

// ---------------- helpers (all sm_80-era PTX) ------------------------------
__device__ __forceinline__ uint32_t smem_u32(const void* p) {
    uint32_t a;
    asm("{ .reg .u64 t; cvta.to.shared.u64 t, %1; cvt.u32.u64 %0, t; }"
        : "=r"(a) : "l"(p));
    return a;
}

__device__ __forceinline__ uint32_t lds32(uint32_t a) {
    uint32_t v;
    asm("ld.shared.b32 %0, [%1];" : "=r"(v) : "r"(a));
    return v;
}

__device__ __forceinline__ void mma16816(float* d, const uint32_t* a,
                                         const uint32_t* b) {
    asm("mma.sync.aligned.m16n8k16.row.col.f32.bf16.bf16.f32 "
        "{%0,%1,%2,%3}, {%4,%5,%6,%7}, {%8,%9}, {%0,%1,%2,%3};"
        : "+f"(d[0]), "+f"(d[1]), "+f"(d[2]), "+f"(d[3])
        : "r"(a[0]), "r"(a[1]), "r"(a[2]), "r"(a[3]), "r"(b[0]), "r"(b[1]));
}

#define CPA16(dst, src, sz) \
    asm volatile("cp.async.ca.shared.global [%0], [%1], 16, %2;" \
                 :: "r"(dst), "l"(src), "r"(sz) : "memory")
#define CPA_COMMIT() asm volatile("cp.async.commit_group;" ::: "memory")
#define CPA_WAIT0()  asm volatile("cp.async.wait_group 0;" ::: "memory")

// ---------------------------------------------------------------------------
// prep_w: w1/w2 -> split-bf16, K reordered [co][pq][ci]
// ---------------------------------------------------------------------------
__global__ void prep_w_kernel(const float* __restrict__ w1,
                              const float* __restrict__ w2)
{
    const int idx = blockIdx.x * 256 + threadIdx.x;
    if (idx >= 384 * KDIM) return;
    const int co = idx / KDIM;
    const int k  = idx - co * KDIM;          // k' = pq*128 + ci
    const int pq = k >> 7;
    const int ci = k & 127;
    const float v = (co < 128) ? w1[co * KDIM + ci * 9 + pq]
                               : w2[(co - 128) * KDIM + ci * 9 + pq];
    const __nv_bfloat16 h = __float2bfloat16(v);
    g_wh[idx] = h;
    g_wl[idx] = __float2bfloat16(v - __bfloat162float(h));
}

// ---------------------------------------------------------------------------
// prep_x: NCHW f32 -> NHWC split-bf16 (tile transpose through smem)
// grid (12, 384, 4), block 256
// ---------------------------------------------------------------------------
__global__ void prep_x_kernel(const float* __restrict__ x)
{
    __shared__ float tile[128][33];
    const int b = blockIdx.z, h = blockIdx.y, w0 = blockIdx.x * 32;
    const int t = threadIdx.x;

    {   // load 128c x 32w
        const int wl = t & 31, c0 = (t >> 5) * 16;
        const float* src = x + ((size_t)(b * 128 + c0) * 384 + h) * 384 + w0 + wl;
        #pragma unroll
        for (int i = 0; i < 16; i++) tile[c0 + i][wl] = src[(size_t)i * 147456];
    }
    __syncthreads();
    {   // write NHWC
        const int wl = t >> 3, c0 = (t & 7) * 16;
        const size_t obase = ((size_t)(b * 384 + h) * 384 + w0 + wl) * 128 + c0;
        #pragma unroll
        for (int i = 0; i < 16; i++) {
            const float v = tile[c0 + i][wl];
            const __nv_bfloat16 hh = __float2bfloat16(v);
            g_xh[obase + i] = hh;
            g_xl[obase + i] = __float2bfloat16(v - __bfloat162float(hh));
        }
    }
}

// ---------------------------------------------------------------------------
// conv_mma: mma.sync bf16 split GEMM.
// Grid (3 Mtiles, 4608 Ntiles), 256 threads (8 warps, 2x4), ~129KB smem.
// Stage s (18): pq = s/2, ci0 = (s&1)*64. Tiles Ah/Al/Bh/Bl: 128 rows x
// 64 bf16 (128B rows, SW128 XOR swizzle). cp.async double buffered.
// ---------------------------------------------------------------------------
#define CV_SMEM_BYTES (1024 + 2 * 65536)

__global__ __launch_bounds__(256, 1)
void conv_mma_kernel()
{
    extern __shared__ char dsm_raw[];
    char* dsm = (char*)(((uintptr_t)dsm_raw + 1023) & ~(uintptr_t)1023);
    const uint32_t sb = smem_u32(dsm);

    const int tid  = threadIdx.x;
    const int wid  = tid >> 5;
    const int lane = tid & 31;
    const int wm = wid >> 2;          // 0..1  (M)
    const int wn = wid & 3;           // 0..3  (N)
    const int g  = lane >> 2;         // 0..7
    const int t  = lane & 3;          // 0..3

    // geometry
    const int co0 = blockIdx.x * 128;
    const int n0  = blockIdx.y * 128;
    const int b   = n0 / 147456;
    const int rm  = n0 - b * 147456;
    const int h   = rm / 384;
    const int w0  = rm - h * 384;

    // loader role: tile lt (0 Ah, 1 Al, 2 Bh, 3 Bl), rows lr and lr+64
    const int lt = tid >> 6;
    const int lr = tid & 63;
    const bool isA = (lt < 2);
    const __nv_bfloat16* wsrc = (lt == 0) ? g_wh : g_wl;
    const __nv_bfloat16* xsrc = (lt == 2) ? g_xh : g_xl;

    float acc[4][4][4];
    #pragma unroll
    for (int i = 0; i < 4; i++)
        #pragma unroll
        for (int j = 0; j < 4; j++)
            #pragma unroll
            for (int e = 0; e < 4; e++) acc[i][j][e] = 0.f;

    // ---- cp.async fill of stage S into buffer BUF ----
    #define CP_STAGE(S, BUF) do {                                              \
        const int s_ = (S);                                                    \
        const int pq_ = s_ >> 1;                                               \
        const int p_ = pq_ / 3, q_ = pq_ - p_ * 3;                             \
        const int ci0_ = (s_ & 1) << 6;                                        \
        const uint32_t tb = sb + (BUF) * 65536 + lt * 16384;                   \
        if (isA) {                                                             \
            _Pragma("unroll")                                                  \
            for (int rr = 0; rr < 2; rr++) {                                   \
                const int row = lr + rr * 64;                                  \
                const __nv_bfloat16* src = wsrc +                              \
                    (size_t)(co0 + row) * KDIM + pq_ * 128 + ci0_;             \
                _Pragma("unroll")                                              \
                for (int c = 0; c < 8; c++) {                                  \
                    const uint32_t dst = tb + row * 128 +                      \
                                         ((c ^ (row & 7)) << 4);               \
                    CPA16(dst, src + c * 8, 16);                               \
                }                                                              \
            }                                                                  \
        } else {                                                               \
            const int srow = h + p_ - 1;                                       \
            const bool rok = (unsigned)srow < 384u;                            \
            _Pragma("unroll")                                                  \
            for (int rr = 0; rr < 2; rr++) {                                   \
                const int row = lr + rr * 64;                                  \
                const int scol = w0 + row + q_ - 1;                            \
                const bool v = rok && ((unsigned)scol < 384u);                 \
                const __nv_bfloat16* src = v ? (xsrc +                         \
                    ((size_t)(b * 384 + srow) * 384 + scol) * 128 + ci0_)      \
                    : xsrc;                                                    \
                const int sz = v ? 16 : 0;                                     \
                _Pragma("unroll")                                              \
                for (int c = 0; c < 8; c++) {                                  \
                    const uint32_t dst = tb + row * 128 +                      \
                                         ((c ^ (row & 7)) << 4);               \
                    CPA16(dst, src + c * 8, sz);                               \
                }                                                              \
            }                                                                  \
        }                                                                      \
    } while (0)

    CP_STAGE(0, 0);
    CPA_COMMIT();

    for (int s = 0; s < 18; s++) {
        CPA_WAIT0();
        __syncthreads();
        if (s < 17) {
            CP_STAGE(s + 1, (s + 1) & 1);
            CPA_COMMIT();
        }

        const uint32_t tAh = sb + (s & 1) * 65536;
        const uint32_t tAl = tAh + 16384;
        const uint32_t tBh = tAh + 32768;
        const uint32_t tBl = tAh + 49152;

        #pragma unroll
        for (int ks = 0; ks < 4; ks++) {
            const uint32_t off_lo = ((uint32_t)((2 * ks)     ^ g) << 4) + (t << 2);
            const uint32_t off_hi = ((uint32_t)((2 * ks + 1) ^ g) << 4) + (t << 2);

            uint32_t ah[4][4], al[4][4];
            #pragma unroll
            for (int mt = 0; mt < 4; mt++) {
                const uint32_t r0 = (uint32_t)(wm * 64 + mt * 16 + g) * 128;
                ah[mt][0] = lds32(tAh + r0 + off_lo);
                ah[mt][1] = lds32(tAh + r0 + 1024 + off_lo);
                ah[mt][2] = lds32(tAh + r0 + off_hi);
                ah[mt][3] = lds32(tAh + r0 + 1024 + off_hi);
                al[mt][0] = lds32(tAl + r0 + off_lo);
                al[mt][1] = lds32(tAl + r0 + 1024 + off_lo);
                al[mt][2] = lds32(tAl + r0 + off_hi);
                al[mt][3] = lds32(tAl + r0 + 1024 + off_hi);
            }
            uint32_t bh[4][2], bl[4][2];
            #pragma unroll
            for (int nt = 0; nt < 4; nt++) {
                const uint32_t rb = (uint32_t)(wn * 32 + nt * 8 + g) * 128;
                bh[nt][0] = lds32(tBh + rb + off_lo);
                bh[nt][1] = lds32(tBh + rb + off_hi);
                bl[nt][0] = lds32(tBl + rb + off_lo);
                bl[nt][1] = lds32(tBl + rb + off_hi);
            }
            #pragma unroll
            for (int mt = 0; mt < 4; mt++)
                #pragma unroll
                for (int nt = 0; nt < 4; nt++)
                    mma16816(acc[mt][nt], ah[mt], bh[nt]);
            #pragma unroll
            for (int mt = 0; mt < 4; mt++)
                #pragma unroll
                for (int nt = 0; nt < 4; nt++)
                    mma16816(acc[mt][nt], ah[mt], bl[nt]);
            #pragma unroll
            for (int mt = 0; mt < 4; mt++)
                #pragma unroll
                for (int nt = 0; nt < 4; nt++)
                    mma16816(acc[mt][nt], al[mt], bh[nt]);
        }
        __syncthreads();   // all reads of this buffer done before refill
    }

    // ---- epilogue: registers -> g_Y (phase-major fp32) ----
    const int hm3 = h % 3, hd = h / 3;
    #pragma unroll
    for (int mt = 0; mt < 4; mt++) {
        const int co_r = co0 + wm * 64 + mt * 16 + g;
        const size_t base0 = ((size_t)(b * 384) + co_r) * 9;
        const size_t base1 = base0 + (size_t)8 * 9;
        #pragma unroll
        for (int nt = 0; nt < 4; nt++) {
            const int w = w0 + wn * 32 + nt * 8 + t * 2;
            const int kp0 = hm3 * 3 + (w % 3);
            const int kp1 = hm3 * 3 + ((w + 1) % 3);
            const size_t c0 = (size_t)hd * 128 + (w / 3);
            const size_t c1 = (size_t)hd * 128 + ((w + 1) / 3);
            g_Y[(base0 + kp0) * 16384 + c0] = acc[mt][nt][0];
            g_Y[(base0 + kp1) * 16384 + c1] = acc[mt][nt][1];
            g_Y[(base1 + kp0) * 16384 + c0] = acc[mt][nt][2];
            g_Y[(base1 + kp1) * 16384 + c1] = acc[mt][nt][3];
        }
    }
}

// ---------------------------------------------------------------------------
// gram (SIMT fp32): per (b,k) C[o,i] = sum_l y2 y1
// ---------------------------------------------------------------------------
__global__ __launch_bounds__(256, 2)
void gram_kernel()
{
    __shared__ float As[2][8][128];
    __shared__ float Bs[2][8][128];

    const int tid = threadIdx.x;
    const int tx = tid & 15;
    const int ty = tid >> 4;

    const int bk = blockIdx.z;
    const int b  = bk / 9;
    const int k  = bk - b * 9;
    const int o0 = blockIdx.y * 128;
    const int l0 = blockIdx.x * 2048;

    const int ld_row = tid >> 1;
    const int ld_col = (tid & 1) * 4;

    const float* Aptr = g_Y + ((size_t)(b * 384 + 128 + o0 + ld_row) * 9 + k) * 16384
                        + l0 + ld_col;
    const float* Bptr = g_Y + ((size_t)(b * 384 + ld_row) * 9 + k) * 16384
                        + l0 + ld_col;

    float acc[8][8];
    #pragma unroll
    for (int i = 0; i < 8; i++)
        #pragma unroll
        for (int j = 0; j < 8; j++) acc[i][j] = 0.f;

    float4 a_reg = *(const float4*)(Aptr);
    float4 b_reg = *(const float4*)(Bptr);
    As[0][ld_col + 0][ld_row] = a_reg.x;
    As[0][ld_col + 1][ld_row] = a_reg.y;
    As[0][ld_col + 2][ld_row] = a_reg.z;
    As[0][ld_col + 3][ld_row] = a_reg.w;
    Bs[0][ld_col + 0][ld_row] = b_reg.x;
    Bs[0][ld_col + 1][ld_row] = b_reg.y;
    Bs[0][ld_col + 2][ld_row] = b_reg.z;
    Bs[0][ld_col + 3][ld_row] = b_reg.w;
    __syncthreads();

    for (int kt = 0; kt < 256; kt++) {
        const int cur = kt & 1;
        if (kt < 255) {
            a_reg = *(const float4*)(Aptr + (kt + 1) * 8);
            b_reg = *(const float4*)(Bptr + (kt + 1) * 8);
        }
        #pragma unroll
        for (int kk = 0; kk < 8; kk++) {
            const float4 a0 = *(const float4*)&As[cur][kk][ty * 8];
            const float4 a1 = *(const float4*)&As[cur][kk][ty * 8 + 4];
            const float4 b0 = *(const float4*)&Bs[cur][kk][tx * 8];
            const float4 b1 = *(const float4*)&Bs[cur][kk][tx * 8 + 4];
            const float av[8] = {a0.x, a0.y, a0.z, a0.w, a1.x, a1.y, a1.z, a1.w};
            const float bv[8] = {b0.x, b0.y, b0.z, b0.w, b1.x, b1.y, b1.z, b1.w};
            #pragma unroll
            for (int i = 0; i < 8; i++)
                #pragma unroll
                for (int j = 0; j < 8; j++)
                    acc[i][j] = fmaf(av[i], bv[j], acc[i][j]);
        }
        if (kt < 255) {
            const int nxt = cur ^ 1;
            As[nxt][ld_col + 0][ld_row] = a_reg.x;
            As[nxt][ld_col + 1][ld_row] = a_reg.y;
            As[nxt][ld_col + 2][ld_row] = a_reg.z;
            As[nxt][ld_col + 3][ld_row] = a_reg.w;
            Bs[nxt][ld_col + 0][ld_row] = b_reg.x;
            Bs[nxt][ld_col + 1][ld_row] = b_reg.y;
            Bs[nxt][ld_col + 2][ld_row] = b_reg.z;
            Bs[nxt][ld_col + 3][ld_row] = b_reg.w;
            __syncthreads();
        }
    }

    #pragma unroll
    for (int ii = 0; ii < 8; ii++) {
        const int o = o0 + ty * 8 + ii;
        float* dst = g_logits + ((size_t)(b * 256 + o) * 128) * 9 + k;
        #pragma unroll
        for (int jj = 0; jj < 8; jj++) {
            const int i = tx * 8 + jj;
            atomicAdd(dst + (size_t)i * 9, acc[ii][jj]);
        }
    }
}

__global__ void zero_logits_kernel()
{
    const int i = blockIdx.x * 256 + threadIdx.x;
    if (i < 4 * 256 * 128 * 9) g_logits[i] = 0.f;
}

__global__ void softmax_kernel(float* __restrict__ out)
{
    const int row = blockIdx.x;
    const float* in = g_logits + (size_t)row * 1152;
    float* op = out + (size_t)row * 1152;
    const float sc = 0.029462782549439484f;     // 1/sqrt(1152)

    __shared__ float red[256];
    const int tid = threadIdx.x;

    float m = -1e30f;
    for (int j = tid; j < 1152; j += 256) m = fmaxf(m, in[j] * sc);
    red[tid] = m;
    __syncthreads();
    for (int s = 128; s > 0; s >>= 1) {
        if (tid < s) red[tid] = fmaxf(red[tid], red[tid + s]);
        __syncthreads();
    }
    m = red[0];
    __syncthreads();

    float sum = 0.f;
    for (int j = tid; j < 1152; j += 256) {
        const float e = expf(in[j] * sc - m);
        op[j] = e;
        sum += e;
    }
    red[tid] = sum;
    __syncthreads();
    for (int s = 128; s > 0; s >>= 1) {
        if (tid < s) red[tid] += red[tid + s];
        __syncthreads();
    }
    const float inv = 1.0f / red[0];
    for (int j = tid; j < 1152; j += 256) op[j] *= inv;
}

// ---------------------------------------------------------------------------
extern "C" void kernel_launch(void* const* d_in, const int* in_sizes, int n_in,
                              void* d_out, int out_size)
{
    const float* x  = (const float*)d_in[0];
    const float* w1 = (const float*)d_in[1];
    const float* w2 = (const float*)d_in[2];
    float* out = (float*)d_out;

    cudaFuncSetAttribute(conv_mma_kernel,
                         cudaFuncAttributeMaxDynamicSharedMemorySize,
                         CV_SMEM_BYTES);

    prep_w_kernel<<<1728, 256>>>(w1, w2);
    prep_x_kernel<<<dim3(12, 384, 4), 256>>>(x);
    conv_mma_kernel<<<dim3(3, 4608), 256, CV_SMEM_BYTES>>>();
    zero_logits_kernel<<<4608, 256>>>();
    gram_kernel<<<dim3(8, 2, 36), 256>>>();
    softmax_kernel<<<1024, 256>>>(out);
}